// round 15
// baseline (speedup 1.0000x reference)
#include <cuda_runtime.h>
#include <math.h>

// Problem constants
#define NB 32     // batch
#define SS 12     // seq len
#define FF 128    // features
#define KH 8      // heads
#define HH 64     // head dim
#define CC 64     // out channels
#define NN 512    // nodes
#define SEGS 16   // n-segments per c2 (512/16 = 32 rows/segment) -- R7 stream shape

#define FEAT_BLOCKS NB            // 32 feature blocks FIRST (wave-1 placement)
#define WF_BLOCKS (CC * SEGS)     // 1024 stream blocks
#define TOTAL_BLOCKS (FEAT_BLOCKS + WF_BLOCKS)   // 1056

// Scratch (no allocations allowed)
__device__ float g_wfpart[CC * SEGS * CC];  // partials [c2][seg][c] (256 KB)
__device__ unsigned int g_scount;           // stream-done counter (zero-init)
__device__ unsigned int g_fdone;            // feature-done counter (for reset)

// Shared union:
//   stream:  sred 1024 floats
//   feature: phase1 2944 floats; finale sw 4096 + sv 64 + red 256 = 4416
#define SBUF_FLOATS 4416

__global__ void __launch_bounds__(256) kOne(
    const float* __restrict__ Wf,
    const float* __restrict__ x,
    const float* __restrict__ W_heads,
    const float* __restrict__ W_out,
    const float* __restrict__ bf,
    float* __restrict__ out)
{
    __shared__ __align__(16) float sbuf[SBUF_FLOATS];
    int bid = blockIdx.x;
    int tid = threadIdx.x;

    if (bid >= FEAT_BLOCKS) {
        // ============== stream role: R7 shape, untouched, exit-after-write =====
        int wb  = bid - FEAT_BLOCKS;
        int c2  = wb >> 4;           // 0..63
        int seg = wb & 15;           // 0..15
        int lane = tid & 15;         // float4 index within 64-float row
        int np   = tid >> 4;         // 16 n-partitions, 2 rows each

        const float4* base = (const float4*)(Wf + (size_t)c2 * (NN * CC));

        float4 acc;
        {
            int n0 = seg * 32 + np * 2;
            float4 v0 = base[(n0 + 0) * 16 + lane];
            float4 v1 = base[(n0 + 1) * 16 + lane];
            acc.x = v0.x + v1.x; acc.y = v0.y + v1.y;
            acc.z = v0.z + v1.z; acc.w = v0.w + v1.w;
        }

        float4* sred = (float4*)sbuf;
        sred[tid] = acc;
        __syncthreads();
        #pragma unroll
        for (int s = 8; s >= 1; s >>= 1) {
            if (np < s) {
                float4 o = sred[(np + s) * 16 + lane];
                float4 m = sred[np * 16 + lane];
                m.x += o.x; m.y += o.y; m.z += o.z; m.w += o.w;
                sred[np * 16 + lane] = m;
            }
            __syncthreads();
        }
        if (tid < 16) {
            ((float4*)(g_wfpart + ((size_t)c2 * SEGS + seg) * CC))[lane] = sred[lane];
        }

        // publish partial, bump counter, exit
        __threadfence();
        __syncthreads();
        if (tid == 0) atomicAdd(&g_scount, 1u);
        return;
    }

    // ============== feature role + finale for this batch row =================
    int b = bid;

    // ---- phase 1: v[b][c] = sum_j elu( x_last[b] . W_heads[:,:,j] ) * W_out[j][c]
    {
        float* xl    = sbuf;                 // 128
        float* hpart = sbuf + 128;           // [4 fparts][512 j]
        float* hp    = sbuf + 128 + 2048;    // 512
        float* red   = sbuf + 128 + 2048 + 512; // 256

        if (tid < 32)
            ((float4*)xl)[tid] = ((const float4*)(x + b * SS * FF + (SS - 1) * FF))[tid];
        __syncthreads();

        #pragma unroll
        for (int s = 0; s < 2; ++s) {
            int slot  = tid + s * 256;       // 0..511
            int fpart = slot >> 7;           // 0..3
            int jq    = slot & 127;          // j-quad
            int k     = jq >> 4;             // head index
            int h0    = (jq & 15) * 4;
            const float4* w = (const float4*)(W_heads + (size_t)k * FF * HH + h0);
            int f0 = fpart * 32;
            float4 acc = make_float4(0.f, 0.f, 0.f, 0.f);
            #pragma unroll 8
            for (int i = 0; i < 32; ++i) {
                float4 wv = w[(f0 + i) * 16];
                float xv = xl[f0 + i];
                acc.x = fmaf(xv, wv.x, acc.x);
                acc.y = fmaf(xv, wv.y, acc.y);
                acc.z = fmaf(xv, wv.z, acc.z);
                acc.w = fmaf(xv, wv.w, acc.w);
            }
            ((float4*)hpart)[fpart * 128 + jq] = acc;
        }
        __syncthreads();

        #pragma unroll
        for (int s = 0; s < 2; ++s) {
            int j = tid + s * 256;
            float sum = (hpart[j] + hpart[512 + j]) + (hpart[1024 + j] + hpart[1536 + j]);
            hp[j] = (sum > 0.f) ? sum : expm1f(sum);   // elu (alpha=1)
        }
        __syncthreads();

        {
            int c = tid & 63;
            int part = tid >> 6;
            int j0 = part * 128;
            float acc0 = 0.f, acc1 = 0.f;
            #pragma unroll 16
            for (int j = 0; j < 64; ++j) {
                acc0 = fmaf(hp[j0 + j],      W_out[(j0 + j) * CC + c],      acc0);
                acc1 = fmaf(hp[j0 + 64 + j], W_out[(j0 + 64 + j) * CC + c], acc1);
            }
            red[part * 64 + c] = acc0 + acc1;
        }
        __syncthreads();
        #pragma unroll
        for (int s = 2; s >= 1; s >>= 1) {
            int c = tid & 63;
            int part = tid >> 6;
            if (part < s) red[part * 64 + c] += red[(part + s) * 64 + c];
            __syncthreads();
        }
    }
    // v[b][*] now in sbuf[2688..2751] (red[0..63]). Save it before re-using sbuf.
    float vreg = sbuf[128 + 2048 + 512 + tid % 64];   // each thread keeps v[c=tid%64]
    __syncthreads();

    // new layout for finale
    float* sw  = sbuf;            // 4096: Wfsum [c2][c]
    float* sv  = sbuf + 4096;     // 64:   v[b][c]
    float* red = sbuf + 4160;     // 256

    if (tid < CC) sv[tid] = vreg; // threads 0..63 hold v[c=tid]
    float bias = (tid < CC) ? bf[tid] : 0.f;   // bf[c2=tid] for output phase

    // ---- wait for all stream partials ----
    if (tid == 0) {
        while (atomicAdd(&g_scount, 0u) < (unsigned)WF_BLOCKS) { }
    }
    __syncthreads();
    __threadfence();   // acquire

    // ---- reduce partials: sw[c2][c] = sum_seg g_wfpart[c2][seg][c] ----
    // 1024 float4 outputs (64 c2 x 16 lanes); 4 per thread; 16 L2 loads each.
    const float4* p4 = (const float4*)g_wfpart;
    #pragma unroll
    for (int k = 0; k < 4; ++k) {
        int item = tid + k * 256;     // 0..1023
        int c2i  = item >> 4;
        int ln   = item & 15;
        const float4* row = p4 + (size_t)c2i * (SEGS * 16) + ln;
        float4 s0 = make_float4(0.f, 0.f, 0.f, 0.f);
        float4 s1 = make_float4(0.f, 0.f, 0.f, 0.f);
        #pragma unroll
        for (int seg = 0; seg < SEGS; seg += 2) {
            float4 t0 = row[(seg + 0) * 16];
            float4 t1 = row[(seg + 1) * 16];
            s0.x += t0.x; s0.y += t0.y; s0.z += t0.z; s0.w += t0.w;
            s1.x += t1.x; s1.y += t1.y; s1.z += t1.z; s1.w += t1.w;
        }
        float4 s;
        s.x = s0.x + s1.x; s.y = s0.y + s1.y;
        s.z = s0.z + s1.z; s.w = s0.w + s1.w;
        ((float4*)sw)[item] = s;
    }
    __syncthreads();

    // ---- out[b][c2] = bf[c2] + dot(v, sw[c2]) ----
    // thread -> (c2 = tid&63, part = tid>>6): 16 c's each, then smem reduce.
    {
        int c2 = tid & 63;
        int part = tid >> 6;
        const float* swr = sw + c2 * CC + part * 16;
        const float* svp = sv + part * 16;
        float acc = 0.f;
        #pragma unroll
        for (int c = 0; c < 16; ++c)
            acc = fmaf(svp[c], swr[c], acc);
        red[part * 64 + c2] = acc;
    }
    __syncthreads();
    if (tid < CC) {
        float o = ((red[tid] + red[64 + tid]) + (red[128 + tid] + red[192 + tid])) + bias;
        out[b * CC + tid] = o;
    }

    // ---- reset counters for next graph replay ----
    __syncthreads();
    if (tid == 0) {
        unsigned int f = atomicAdd(&g_fdone, 1u);
        if (f == FEAT_BLOCKS - 1) {   // last feature block; everyone else done
            g_fdone  = 0u;
            g_scount = 0u;
            __threadfence();
        }
    }
}

// ---------------------------------------------------------------------------
// Inputs (metadata order):
//   0: x        (32,12,128)   f32
//   1: W_heads  (8,128,64)    f32
//   2: a1_heads (8,64)        f32   (unused: softmax over identical rows is uniform)
//   3: a2_heads (8,64)        f32   (unused)
//   4: W_out    (512,64)      f32
//   5: a1_out   (64)          f32   (unused)
//   6: a2_out   (64)          f32   (unused)
//   7: Wf       (64,32768)    f32
//   8: bf       (64)          f32
// Output: (32,64) f32
// ---------------------------------------------------------------------------
extern "C" void kernel_launch(void* const* d_in, const int* in_sizes, int n_in,
                              void* d_out, int out_size)
{
    const float* x       = (const float*)d_in[0];
    const float* W_heads = (const float*)d_in[1];
    const float* W_out   = (const float*)d_in[4];
    const float* Wf      = (const float*)d_in[7];
    const float* bf      = (const float*)d_in[8];
    float* out = (float*)d_out;

    kOne<<<TOTAL_BLOCKS, 256>>>(Wf, x, W_heads, W_out, bf, out);
}

// round 16
// speedup vs baseline: 1.8246x; 1.8246x over previous
#include <cuda_runtime.h>
#include <math.h>

// Problem constants
#define NB 32     // batch
#define SS 12     // seq len
#define FF 128    // features
#define KH 8      // heads
#define HH 64     // head dim
#define CC 64     // out channels
#define NN 512    // nodes
#define SEGS 16   // n-segments for Wf reduction (512/16 = 32 rows/segment)

#define FEAT_BLOCKS NB                    // 32 feature blocks FIRST (overlap with stream)
#define WF_BLOCKS (CC * SEGS)             // 1024 stream blocks
#define TOTAL_BLOCKS (FEAT_BLOCKS + WF_BLOCKS)

// Scratch (no allocations allowed)
__device__ float g_v[NB * CC];              // per-batch feature vector v[b][c]
__device__ float g_wfpart[CC * SEGS * CC];  // partials, layout [c2][seg][c]

// ---------------------------------------------------------------------------
// Kernel A (block-specialized, R7 structure; stream reduce now 1-sync):
//   blocks [0, 32):       per-batch features (latency-optimized, f-parallel)
//   blocks [32, 32+1024):  g_wfpart[c2][seg][c] = sum_{n in seg} Wf[c2][n*64+c]
// ---------------------------------------------------------------------------
__global__ void __launch_bounds__(256) kA_fused(
    const float* __restrict__ Wf,
    const float* __restrict__ x,
    const float* __restrict__ W_heads,
    const float* __restrict__ W_out)
{
    __shared__ __align__(16) float sbuf[128 + 2048 + 512 + 256];
    int bid = blockIdx.x;
    int tid = threadIdx.x;

    if (bid >= FEAT_BLOCKS) {
        // ---------------- Wf segment reduction (1 sync) ----------------
        int wb  = bid - FEAT_BLOCKS;
        int c2  = wb >> 4;           // 0..63
        int seg = wb & 15;           // 0..15
        int lane = tid & 15;         // float4 index within 64-float row
        int np   = tid >> 4;         // 16 n-partitions, 2 rows each

        const float4* base = (const float4*)(Wf + (size_t)c2 * (NN * CC));

        float4 acc;
        {
            int n0 = seg * 32 + np * 2;
            float4 v0 = base[(n0 + 0) * 16 + lane];
            float4 v1 = base[(n0 + 1) * 16 + lane];
            acc.x = v0.x + v1.x; acc.y = v0.y + v1.y;
            acc.z = v0.z + v1.z; acc.w = v0.w + v1.w;
        }

        float4* sred = (float4*)sbuf;      // [np][lane]
        sred[tid] = acc;
        __syncthreads();

        // threads 0..15: serially fold the 16 np-partials for one lane
        if (tid < 16) {
            float4 s = sred[tid];          // np=0
            #pragma unroll
            for (int p = 1; p < 16; ++p) {
                float4 t = sred[p * 16 + tid];
                s.x += t.x; s.y += t.y; s.z += t.z; s.w += t.w;
            }
            ((float4*)(g_wfpart + ((size_t)c2 * SEGS + seg) * CC))[tid] = s;
        }
    } else {
        // ---------------- per-batch feature vector (R7 verbatim) -------------
        // v[b][c] = sum_j elu( x_last[b] . W_heads[:,:,j] ) * W_out[j][c]
        int b = bid;

        float* xl    = sbuf;                 // 128
        float* hpart = sbuf + 128;           // [4 fparts][512 j]
        float* hp    = sbuf + 128 + 2048;    // 512
        float* red   = sbuf + 128 + 2048 + 512; // 256

        if (tid < 32)
            ((float4*)xl)[tid] = ((const float4*)(x + b * SS * FF + (SS - 1) * FF))[tid];
        __syncthreads();

        #pragma unroll
        for (int s = 0; s < 2; ++s) {
            int slot  = tid + s * 256;       // 0..511
            int fpart = slot >> 7;           // 0..3
            int jq    = slot & 127;          // j-quad
            int k     = jq >> 4;             // head index
            int h0    = (jq & 15) * 4;
            const float4* w = (const float4*)(W_heads + (size_t)k * FF * HH + h0);
            int f0 = fpart * 32;
            float4 acc = make_float4(0.f, 0.f, 0.f, 0.f);
            #pragma unroll 8
            for (int i = 0; i < 32; ++i) {
                float4 wv = w[(f0 + i) * 16];
                float xv = xl[f0 + i];
                acc.x = fmaf(xv, wv.x, acc.x);
                acc.y = fmaf(xv, wv.y, acc.y);
                acc.z = fmaf(xv, wv.z, acc.z);
                acc.w = fmaf(xv, wv.w, acc.w);
            }
            ((float4*)hpart)[fpart * 128 + jq] = acc;
        }
        __syncthreads();

        #pragma unroll
        for (int s = 0; s < 2; ++s) {
            int j = tid + s * 256;
            float sum = (hpart[j] + hpart[512 + j]) + (hpart[1024 + j] + hpart[1536 + j]);
            hp[j] = (sum > 0.f) ? sum : expm1f(sum);   // elu (alpha=1)
        }
        __syncthreads();

        {
            int c = tid & 63;
            int part = tid >> 6;
            int j0 = part * 128;
            float acc0 = 0.f, acc1 = 0.f;
            #pragma unroll 16
            for (int j = 0; j < 64; ++j) {
                acc0 = fmaf(hp[j0 + j],      W_out[(j0 + j) * CC + c],      acc0);
                acc1 = fmaf(hp[j0 + 64 + j], W_out[(j0 + 64 + j) * CC + c], acc1);
            }
            red[part * 64 + c] = acc0 + acc1;
        }
        __syncthreads();
        #pragma unroll
        for (int s = 2; s >= 1; s >>= 1) {
            int c = tid & 63;
            int part = tid >> 6;
            if (part < s) red[part * 64 + c] += red[(part + s) * 64 + c];
            __syncthreads();
        }
        if (tid < CC) g_v[b * CC + tid] = red[tid];
    }
}

// ---------------------------------------------------------------------------
// Kernel B: final output. Grid = 64 blocks (c2), 256 threads.
// One load batch: 1 partial float4 + 2 v float4 per thread.
// ---------------------------------------------------------------------------
__global__ void __launch_bounds__(256) kB_final(
    const float* __restrict__ bf,
    float* __restrict__ out)
{
    int c2 = blockIdx.x;
    int tid = threadIdx.x;

    __shared__ float4 tmp[SEGS * 16];    // 256 float4: partials for this c2
    __shared__ float  sv[NB * CC];       // all v
    __shared__ float  sw[CC];

    // one batch of independent global loads
    const float4* pp = (const float4*)(g_wfpart + (size_t)c2 * SEGS * CC);
    float4 p0 = pp[tid];
    const float4* vp = (const float4*)g_v;
    float4 v0 = vp[tid];
    float4 v1 = vp[tid + 256];
    float bias = bf[c2];

    tmp[tid] = p0;
    ((float4*)sv)[tid]       = v0;
    ((float4*)sv)[tid + 256] = v1;
    __syncthreads();

    // sw[c] = sum over 16 segs (64 threads, one per c)
    if (tid < CC) {
        const float* t = (const float*)tmp;
        float w = 0.f;
        #pragma unroll
        for (int s = 0; s < SEGS; ++s)
            w += t[s * CC + tid];
        sw[tid] = w;
    }
    __syncthreads();

    // out[b][c2]: tid -> b = tid/8, part = tid%8 (8 c's each), shuffle-reduce
    {
        int b = tid >> 3;
        int part = tid & 7;
        const float* svb = sv + b * CC + part * 8;
        const float* swp = sw + part * 8;
        float acc = 0.f;
        #pragma unroll
        for (int c = 0; c < 8; ++c)
            acc = fmaf(svb[c], swp[c], acc);
        acc += __shfl_xor_sync(0xffffffffu, acc, 1);
        acc += __shfl_xor_sync(0xffffffffu, acc, 2);
        acc += __shfl_xor_sync(0xffffffffu, acc, 4);
        if (part == 0)
            out[b * CC + c2] = acc + bias;
    }
}

// ---------------------------------------------------------------------------
// Inputs (metadata order):
//   0: x        (32,12,128)   f32
//   1: W_heads  (8,128,64)    f32
//   2: a1_heads (8,64)        f32   (unused: softmax over identical rows is uniform)
//   3: a2_heads (8,64)        f32   (unused)
//   4: W_out    (512,64)      f32
//   5: a1_out   (64)          f32   (unused)
//   6: a2_out   (64)          f32   (unused)
//   7: Wf       (64,32768)    f32
//   8: bf       (64)          f32
// Output: (32,64) f32
// ---------------------------------------------------------------------------
extern "C" void kernel_launch(void* const* d_in, const int* in_sizes, int n_in,
                              void* d_out, int out_size)
{
    const float* x       = (const float*)d_in[0];
    const float* W_heads = (const float*)d_in[1];
    const float* W_out   = (const float*)d_in[4];
    const float* Wf      = (const float*)d_in[7];
    const float* bf      = (const float*)d_in[8];
    float* out = (float*)d_out;

    kA_fused<<<TOTAL_BLOCKS, 256>>>(Wf, x, W_heads, W_out);
    kB_final<<<CC, 256>>>(bf, out);
}